// round 15
// baseline (speedup 1.0000x reference)
#include <cuda_runtime.h>
#include <cuda_fp16.h>
#include <cstdint>

// Problem constants
static constexpr int Bb = 2048, Tt = 281, Kk = 272, Nn = 272;

#define THREADS 192
static constexpr int BM = 96, BN = 96, BK = 32;      // CTA tile; BK floats of K per chunk
static constexpr int STAGES = 6;
static constexpr int KIT = 9;            // chunks per tile (last is 16-wide)
static constexpr int NKC = Kk / 16;      // 17 k16-chunks
static constexpr int NNB = Nn / 8;       // 34 n8-blocks
static constexpr int NBL = BN / 8;       // 12 n-blocks per CTA

// SMEM layout (bytes, dynamic):
// X stage: 96 rows x 64B (32 fp16), 16B units XOR-swizzled: unit' = unit ^ ((row>>1)&3)
static constexpr int XROW_B   = 64;
static constexpr int XSTAGE_B = BM * XROW_B;          // 6144
static constexpr int WSTAGE_B = NBL * 2 * 256;        // 6144
static constexpr int STAGE_B  = XSTAGE_B + WSTAGE_B;  // 12288
static constexpr int SMEM_BYTES = STAGES * STAGE_B;   // 73728

// Fragment-ordered fp16(RN) weights: per (e, nb, kc16, lane) one uint2
__device__ uint2 g_Wf[4 * NNB * NKC * 32];
__device__ int g_subj_is64;

// One-time W -> fragment-ordered fp16 layout (+ subject dtype probe in block 0)
__global__ void prep_w_frag(const float* __restrict__ W,
                            const unsigned int* __restrict__ subj_words) {
    if (blockIdx.x == 0 && threadIdx.x == 0) {
        int is64 = 1;
        for (int i = 1; i < 2048; i += 2)
            if (subj_words[i] != 0u) { is64 = 0; break; }
        g_subj_is64 = is64;
    }
    int idx = blockIdx.x * blockDim.x + threadIdx.x;
    if (idx >= 4 * NNB * NKC * 32) return;
    int lane = idx & 31;
    int kc   = (idx >> 5) % NKC;
    int nb   = ((idx >> 5) / NKC) % NNB;
    int e    = (idx >> 5) / (NKC * NNB);
    int gid = lane >> 2, tig = lane & 3;
    int n  = nb * 8 + gid;
    int k0 = kc * 16 + 2 * tig;
    const float* We = W + (size_t)e * Kk * Nn;
    __half2 h0 = __floats2half2_rn(We[(size_t)(k0    ) * Nn + n],
                                   We[(size_t)(k0 + 1) * Nn + n]);
    __half2 h1 = __floats2half2_rn(We[(size_t)(k0 + 8) * Nn + n],
                                   We[(size_t)(k0 + 9) * Nn + n]);
    uint2 u;
    u.x = *reinterpret_cast<uint32_t*>(&h0);
    u.y = *reinterpret_cast<uint32_t*>(&h1);
    g_Wf[((size_t)(e * NNB + nb) * NKC + kc) * 32 + lane] = u;
}

__device__ __forceinline__ void mma_f16(float* d, const uint32_t* a, const uint32_t* bfr) {
    asm volatile(
        "mma.sync.aligned.m16n8k16.row.col.f32.f16.f16.f32 "
        "{%0,%1,%2,%3}, {%4,%5,%6,%7}, {%8,%9}, {%0,%1,%2,%3};"
        : "+f"(d[0]), "+f"(d[1]), "+f"(d[2]), "+f"(d[3])
        : "r"(a[0]), "r"(a[1]), "r"(a[2]), "r"(a[3]), "r"(bfr[0]), "r"(bfr[1]));
}
__device__ __forceinline__ void cp_async16(uint32_t dst, const void* src, int sz) {
    asm volatile("cp.async.cg.shared.global [%0], [%1], 16, %2;\n"
                 :: "r"(dst), "l"(src), "r"(sz));
}
__device__ __forceinline__ void ldmatrix_x4(uint32_t& d0, uint32_t& d1,
                                            uint32_t& d2, uint32_t& d3, uint32_t addr) {
    asm volatile("ldmatrix.sync.aligned.m8n8.x4.shared.b16 {%0,%1,%2,%3}, [%4];"
                 : "=r"(d0), "=r"(d1), "=r"(d2), "=r"(d3) : "r"(addr));
}

__global__ __launch_bounds__(THREADS, 3) void subj_gemm_kernel(
    const float* __restrict__ X, const void* __restrict__ subj,
    const float* __restrict__ bias, float* __restrict__ out)
{
    extern __shared__ char smem[];
    const uint32_t xsmem = (uint32_t)__cvta_generic_to_shared(smem);

    const int b   = blockIdx.z;
    const int m0  = blockIdx.y * BM;
    const int nb0 = blockIdx.x * NBL;
    const int n0  = nb0 * 8;

    int s;
    if (g_subj_is64) s = (int)((const long long*)subj)[b];
    else             s = ((const int*)subj)[b];

    const float* Xb  = X + (size_t)b * Tt * Kk;
    const char*  Wfe = reinterpret_cast<const char*>(g_Wf + (size_t)s * NNB * NKC * 32);

    const int tid  = threadIdx.x;
    const int lane = tid & 31;
    const int warp = tid >> 5;     // 0..5
    const int wm   = warp / 3;     // 0..1
    const int wn   = warp % 3;     // 0..2
    const int rl   = lane & 15;    // ldmatrix row-in-frag
    const int hl   = lane >> 4;    // ldmatrix k-half select

    // X producer coords (coalesced): task c = tid + 192*it, it=0..3
    const int xu   = tid & 7;            // fp32 16B unit (0..7)
    const int u16  = xu >> 1;            // fp16 16B unit (0..3)
    const int h8   = xu & 1;             // 8B half within fp16 unit
    int xr[4], xm[4];
#pragma unroll
    for (int it = 0; it < 4; ++it) {
        xr[it] = (tid >> 3) + 24 * it;           // 0..95
        int m = m0 + xr[it];
        xm[it] = (m < Tt) ? m : (Tt - 1);
    }

    float acc[3][4][4];
#pragma unroll
    for (int i = 0; i < 3; ++i)
#pragma unroll
        for (int j = 0; j < 4; ++j)
#pragma unroll
            for (int k = 0; k < 4; ++k) acc[i][j][k] = 0.f;

    // ---- X: 4 coalesced LDG.128 + cvt to fp16 (held as 4 uint2) ----
    auto ldg_x = [&](int ci, uint2* xvh) {
        const int kf = ci * BK + xu * 4;
        if (kf < Kk) {
#pragma unroll
            for (int it = 0; it < 4; ++it) {
                float4 v = *reinterpret_cast<const float4*>(Xb + (size_t)xm[it] * Kk + kf);
                __half2 h0 = __floats2half2_rn(v.x, v.y);
                __half2 h1 = __floats2half2_rn(v.z, v.w);
                xvh[it].x = *reinterpret_cast<uint32_t*>(&h0);
                xvh[it].y = *reinterpret_cast<uint32_t*>(&h1);
            }
        }
    };
    // ---- X: 4x STS.64 into swizzled tile ----
    auto sts_x = [&](int st, int ci, const uint2* xvh) {
        const int kf = ci * BK + xu * 4;
        if (kf < Kk) {
            char* xbase = smem + st * STAGE_B;
#pragma unroll
            for (int it = 0; it < 4; ++it) {
                int r = xr[it];
                int off = r * XROW_B + ((u16 ^ ((r >> 1) & 3)) << 4) + h8 * 8;
                *reinterpret_cast<uint2*>(xbase + off) = xvh[it];
            }
        }
    };
    // ---- W: cp.async fragment chunks for k-window ci (2 x k16) ----
    auto ldw = [&](int st, int ci) {
        char* wbase = smem + st * STAGE_B + XSTAGE_B;
#pragma unroll
        for (int it = 0; it < 2; ++it) {
            int c   = tid + it * THREADS;         // 0..383
            int nbl = c >> 5;
            int ks  = (c >> 4) & 1;
            int ch  = c & 15;
            int nb  = nb0 + nbl;
            int kc  = ci * 2 + ks;
            bool v  = (nb < NNB) && (kc < NKC);
            const char* src = Wfe + ((size_t)(v ? nb : 0) * NKC + (v ? kc : 0)) * 256 + ch * 16;
            uint32_t dst = (uint32_t)__cvta_generic_to_shared(
                wbase + (nbl * 2 + ks) * 256 + ch * 16);
            cp_async16(dst, src, v ? 16 : 0);
        }
    };

    // ---- prologue: X chunks 0,1 direct; W chunks 0..4 async (1 group each);
    //      X chunks 2,3 held in register buffers A,B ----
    uint2 xvhA[4], xvhB[4];
    ldg_x(0, xvhA); sts_x(0, 0, xvhA);
    ldg_x(1, xvhB); sts_x(1, 1, xvhB);
    ldw(0, 0);
    asm volatile("cp.async.commit_group;" ::: "memory");
    ldw(1, 1);
    asm volatile("cp.async.commit_group;" ::: "memory");
    ldw(2, 2);
    asm volatile("cp.async.commit_group;" ::: "memory");
    ldw(3, 3);
    asm volatile("cp.async.commit_group;" ::: "memory");
    ldg_x(2, xvhA);              // STS at iter 0
    ldg_x(3, xvhB);              // STS at iter 1
    ldw(4, 4);
    asm volatile("cp.async.commit_group;" ::: "memory");

    for (int kk = 0; kk < KIT; ++kk) {
        asm volatile("cp.async.wait_group 3;" ::: "memory");
        __syncthreads();

        const int st = kk % STAGES;
        const uint32_t xbase = xsmem + st * STAGE_B;
        const char* wbase = smem + st * STAGE_B + XSTAGE_B;

        // ---- all W fragments up front (conflict-free LDS.64) ----
        uint32_t bf[2][4][2];
#pragma unroll
        for (int ks = 0; ks < 2; ++ks)
#pragma unroll
            for (int ni = 0; ni < 4; ++ni) {
                int nbl = wn * 4 + ni;
                uint2 v = *reinterpret_cast<const uint2*>(
                    wbase + (nbl * 2 + ks) * 256 + lane * 8);
                bf[ks][ni][0] = v.x;
                bf[ks][ni][1] = v.y;
            }

        // ---- X fragments ks0 via ldmatrix + MMA burst 0 ----
        uint32_t af[3][4];
#pragma unroll
        for (int mi = 0; mi < 3; ++mi) {
            int row = wm * 48 + mi * 16 + rl;
            uint32_t addr = xbase + row * XROW_B
                          + (((0 * 2 + hl) ^ ((row >> 1) & 3)) << 4);
            ldmatrix_x4(af[mi][0], af[mi][1], af[mi][2], af[mi][3], addr);
        }
#pragma unroll
        for (int mi = 0; mi < 3; ++mi)
#pragma unroll
            for (int ni = 0; ni < 4; ++ni)
                mma_f16(acc[mi][ni], af[mi], bf[0][ni]);

        // ---- memory issue phase (overlaps MMA tail) ----
        uint2* bufCur = (kk & 1) ? xvhB : xvhA;   // holds chunk kk+2
        const int s2 = kk + 2;
        if (s2 < KIT) sts_x(s2 % STAGES, s2, bufCur);
        const int s4 = kk + 4;
        if (s4 < KIT) {
            ldg_x(s4, bufCur);                    // refill same buffer, chunk kk+4
            ldw(s4 % STAGES, s4);
        }
        asm volatile("cp.async.commit_group;" ::: "memory");

        // ---- X fragments ks1 + MMA burst 1 (skip on last half-window) ----
        if (kk != KIT - 1) {
#pragma unroll
            for (int mi = 0; mi < 3; ++mi) {
                int row = wm * 48 + mi * 16 + rl;
                uint32_t addr = xbase + row * XROW_B
                              + (((1 * 2 + hl) ^ ((row >> 1) & 3)) << 4);
                ldmatrix_x4(af[mi][0], af[mi][1], af[mi][2], af[mi][3], addr);
            }
#pragma unroll
            for (int mi = 0; mi < 3; ++mi)
#pragma unroll
                for (int ni = 0; ni < 4; ++ni)
                    mma_f16(acc[mi][ni], af[mi], bf[1][ni]);
        }
    }

    // ---- epilogue: bias add + guarded float2 stores ----
    const int gid = lane >> 2;
    const int tig = lane & 3;
    float* outb = out + (size_t)b * Tt * Nn;
    const float* bb = bias + s * Nn;
#pragma unroll
    for (int mi = 0; mi < 3; ++mi) {
        int r0 = m0 + wm * 48 + mi * 16 + gid;
#pragma unroll
        for (int ni = 0; ni < 4; ++ni) {
            int n = n0 + wn * 32 + ni * 8 + tig * 2;
            if (n < Nn) {
                float bv0 = bb[n];
                float bv1 = bb[n + 1];
                if (r0 < Tt) {
                    float2 v = make_float2(acc[mi][ni][0] + bv0, acc[mi][ni][1] + bv1);
                    *reinterpret_cast<float2*>(outb + (size_t)r0 * Nn + n) = v;
                }
                if (r0 + 8 < Tt) {
                    float2 v = make_float2(acc[mi][ni][2] + bv0, acc[mi][ni][3] + bv1);
                    *reinterpret_cast<float2*>(outb + (size_t)(r0 + 8) * Nn + n) = v;
                }
            }
        }
    }
}

extern "C" void kernel_launch(void* const* d_in, const int* in_sizes, int n_in,
                              void* d_out, int out_size) {
    const float* X    = (const float*)d_in[0];
    const void*  subj = d_in[1];
    const float* W    = (const float*)d_in[2];
    const float* bias = (const float*)d_in[3];
    float* out = (float*)d_out;

    cudaFuncSetAttribute(subj_gemm_kernel,
                         cudaFuncAttributeMaxDynamicSharedMemorySize, SMEM_BYTES);

    int prep_threads = 4 * NNB * NKC * 32;   // 73984
    prep_w_frag<<<(prep_threads + 255) / 256, 256>>>(W, (const unsigned int*)subj);

    dim3 grid((Nn + BN - 1) / BN,   // 3
              (Tt + BM - 1) / BM,   // 3
              Bb);                  // 2048
    subj_gemm_kernel<<<grid, dim3(THREADS), SMEM_BYTES>>>(X, subj, bias, out);
}

// round 16
// speedup vs baseline: 1.3471x; 1.3471x over previous
#include <cuda_runtime.h>
#include <cuda_fp16.h>
#include <cstdint>

// Problem constants
static constexpr int Bb = 2048, Tt = 281, Kk = 272, Nn = 272;

#define THREADS 192
static constexpr int BM = 96, BN = 96, BK = 32;      // CTA tile; BK floats of K per chunk
static constexpr int STAGES = 4;
static constexpr int KIT = 9;            // chunks per tile (last is 16-wide)
static constexpr int NKC = Kk / 16;      // 17 k16-chunks
static constexpr int NNB = Nn / 8;       // 34 n8-blocks
static constexpr int NBL = BN / 8;       // 12 n-blocks per CTA

// SMEM layout (bytes, dynamic):
// X stage: 96 rows x 64B (32 fp16), 16B units XOR-swizzled: unit' = unit ^ ((row>>1)&3)
static constexpr int XROW_B   = 64;
static constexpr int XSTAGE_B = BM * XROW_B;          // 6144
static constexpr int WSTAGE_B = NBL * 2 * 256;        // 6144
static constexpr int STAGE_B  = XSTAGE_B + WSTAGE_B;  // 12288
static constexpr int SMEM_BYTES = STAGES * STAGE_B;   // 49152

// Fragment-ordered fp16(RN) weights: per (e, nb, kc16, lane) one uint2
__device__ uint2 g_Wf[4 * NNB * NKC * 32];
__device__ int g_subj_is64;

// One-time W -> fragment-ordered fp16 layout (+ subject dtype probe in block 0)
__global__ void prep_w_frag(const float* __restrict__ W,
                            const unsigned int* __restrict__ subj_words) {
    if (blockIdx.x == 0 && threadIdx.x == 0) {
        int is64 = 1;
        for (int i = 1; i < 2048; i += 2)
            if (subj_words[i] != 0u) { is64 = 0; break; }
        g_subj_is64 = is64;
    }
    int idx = blockIdx.x * blockDim.x + threadIdx.x;
    if (idx >= 4 * NNB * NKC * 32) return;
    int lane = idx & 31;
    int kc   = (idx >> 5) % NKC;
    int nb   = ((idx >> 5) / NKC) % NNB;
    int e    = (idx >> 5) / (NKC * NNB);
    int gid = lane >> 2, tig = lane & 3;
    int n  = nb * 8 + gid;
    int k0 = kc * 16 + 2 * tig;
    const float* We = W + (size_t)e * Kk * Nn;
    __half2 h0 = __floats2half2_rn(We[(size_t)(k0    ) * Nn + n],
                                   We[(size_t)(k0 + 1) * Nn + n]);
    __half2 h1 = __floats2half2_rn(We[(size_t)(k0 + 8) * Nn + n],
                                   We[(size_t)(k0 + 9) * Nn + n]);
    uint2 u;
    u.x = *reinterpret_cast<uint32_t*>(&h0);
    u.y = *reinterpret_cast<uint32_t*>(&h1);
    g_Wf[((size_t)(e * NNB + nb) * NKC + kc) * 32 + lane] = u;
}

__device__ __forceinline__ void mma_f16(float* d, const uint32_t* a, const uint32_t* bfr) {
    asm volatile(
        "mma.sync.aligned.m16n8k16.row.col.f32.f16.f16.f32 "
        "{%0,%1,%2,%3}, {%4,%5,%6,%7}, {%8,%9}, {%0,%1,%2,%3};"
        : "+f"(d[0]), "+f"(d[1]), "+f"(d[2]), "+f"(d[3])
        : "r"(a[0]), "r"(a[1]), "r"(a[2]), "r"(a[3]), "r"(bfr[0]), "r"(bfr[1]));
}
__device__ __forceinline__ void cp_async16(uint32_t dst, const void* src, int sz) {
    asm volatile("cp.async.cg.shared.global [%0], [%1], 16, %2;\n"
                 :: "r"(dst), "l"(src), "r"(sz));
}
__device__ __forceinline__ void ldmatrix_x4(uint32_t& d0, uint32_t& d1,
                                            uint32_t& d2, uint32_t& d3, uint32_t addr) {
    asm volatile("ldmatrix.sync.aligned.m8n8.x4.shared.b16 {%0,%1,%2,%3}, [%4];"
                 : "=r"(d0), "=r"(d1), "=r"(d2), "=r"(d3) : "r"(addr));
}

__global__ __launch_bounds__(THREADS, 3) void subj_gemm_kernel(
    const float* __restrict__ X, const void* __restrict__ subj,
    const float* __restrict__ bias, float* __restrict__ out)
{
    extern __shared__ char smem[];
    const uint32_t xsmem = (uint32_t)__cvta_generic_to_shared(smem);

    const int b   = blockIdx.z;
    const int m0  = blockIdx.y * BM;
    const int nb0 = blockIdx.x * NBL;
    const int n0  = nb0 * 8;

    int s;
    if (g_subj_is64) s = (int)((const long long*)subj)[b];
    else             s = ((const int*)subj)[b];

    const float* Xb  = X + (size_t)b * Tt * Kk;
    const char*  Wfe = reinterpret_cast<const char*>(g_Wf + (size_t)s * NNB * NKC * 32);

    const int tid  = threadIdx.x;
    const int lane = tid & 31;
    const int warp = tid >> 5;     // 0..5
    const int wm   = warp / 3;     // 0..1
    const int wn   = warp % 3;     // 0..2
    const int rl   = lane & 15;    // ldmatrix row-in-frag
    const int hl   = lane >> 4;    // ldmatrix k-half select

    // X producer coords (coalesced): task c = tid + 192*it, it=0..3
    //   row = c>>3 = (tid>>3) + 24*it,  16B-unit-in-row = tid&7 (invariant over it)
    const int xu   = tid & 7;            // fp32 16B unit (0..7)
    const int u16  = xu >> 1;            // fp16 16B unit (0..3)
    const int h8   = xu & 1;             // 8B half within fp16 unit
    int xr[4], xm[4];
#pragma unroll
    for (int it = 0; it < 4; ++it) {
        xr[it] = (tid >> 3) + 24 * it;           // 0..95
        int m = m0 + xr[it];
        xm[it] = (m < Tt) ? m : (Tt - 1);
    }

    float acc[3][4][4];
#pragma unroll
    for (int i = 0; i < 3; ++i)
#pragma unroll
        for (int j = 0; j < 4; ++j)
#pragma unroll
            for (int k = 0; k < 4; ++k) acc[i][j][k] = 0.f;

    // ---- X: 4 coalesced LDG.128 + cvt to fp16 (held as 4 uint2) ----
    auto ldg_x = [&](int ci, uint2* xvh) {
        const int kf = ci * BK + xu * 4;
        if (kf < Kk) {
#pragma unroll
            for (int it = 0; it < 4; ++it) {
                float4 v = *reinterpret_cast<const float4*>(Xb + (size_t)xm[it] * Kk + kf);
                __half2 h0 = __floats2half2_rn(v.x, v.y);
                __half2 h1 = __floats2half2_rn(v.z, v.w);
                xvh[it].x = *reinterpret_cast<uint32_t*>(&h0);
                xvh[it].y = *reinterpret_cast<uint32_t*>(&h1);
            }
        }
    };
    // ---- X: 4x STS.64 into swizzled tile ----
    auto sts_x = [&](int st, int ci, const uint2* xvh) {
        const int kf = ci * BK + xu * 4;
        if (kf < Kk) {
            char* xbase = smem + st * STAGE_B;
#pragma unroll
            for (int it = 0; it < 4; ++it) {
                int r = xr[it];
                int off = r * XROW_B + ((u16 ^ ((r >> 1) & 3)) << 4) + h8 * 8;
                *reinterpret_cast<uint2*>(xbase + off) = xvh[it];
            }
        }
    };
    // ---- W: cp.async fragment chunks for k-window ci (2 x k16) ----
    auto ldw = [&](int st, int ci) {
        char* wbase = smem + st * STAGE_B + XSTAGE_B;
#pragma unroll
        for (int it = 0; it < 2; ++it) {
            int c   = tid + it * THREADS;         // 0..383
            int nbl = c >> 5;
            int ks  = (c >> 4) & 1;
            int ch  = c & 15;
            int nb  = nb0 + nbl;
            int kc  = ci * 2 + ks;
            bool v  = (nb < NNB) && (kc < NKC);
            const char* src = Wfe + ((size_t)(v ? nb : 0) * NKC + (v ? kc : 0)) * 256 + ch * 16;
            uint32_t dst = (uint32_t)__cvta_generic_to_shared(
                wbase + (nbl * 2 + ks) * 256 + ch * 16);
            cp_async16(dst, src, v ? 16 : 0);
        }
    };

    // ---- prologue ----
    uint2 xvh[4];
    ldg_x(0, xvh); sts_x(0, 0, xvh);
    ldw(0, 0);
    asm volatile("cp.async.commit_group;" ::: "memory");
    ldg_x(1, xvh); sts_x(1, 1, xvh);
    ldw(1, 1);
    asm volatile("cp.async.commit_group;" ::: "memory");
    ldg_x(2, xvh);               // STS happens at iter 0
    ldw(2, 2);
    asm volatile("cp.async.commit_group;" ::: "memory");

    // ---- mainloop: fully unrolled (KIT=9, STAGES=4 compile-time) so all stage
    //      bases, swizzle offsets and guards fold to immediates ----
#pragma unroll
    for (int kk = 0; kk < KIT; ++kk) {
        asm volatile("cp.async.wait_group 2;" ::: "memory");
        __syncthreads();

        const int st = kk & 3;
        const uint32_t xbase = xsmem + st * STAGE_B;
        const char* wbase = smem + st * STAGE_B + XSTAGE_B;

        // ---- all W fragments up front (conflict-free LDS.64) ----
        uint32_t bf[2][4][2];
#pragma unroll
        for (int ks = 0; ks < 2; ++ks)
#pragma unroll
            for (int ni = 0; ni < 4; ++ni) {
                int nbl = wn * 4 + ni;
                uint2 v = *reinterpret_cast<const uint2*>(
                    wbase + (nbl * 2 + ks) * 256 + lane * 8);
                bf[ks][ni][0] = v.x;
                bf[ks][ni][1] = v.y;
            }

        // ---- X fragments ks0 via ldmatrix + MMA burst 0 ----
        uint32_t af[3][4];
#pragma unroll
        for (int mi = 0; mi < 3; ++mi) {
            int row = wm * 48 + mi * 16 + rl;
            uint32_t addr = xbase + row * XROW_B
                          + (((0 * 2 + hl) ^ ((row >> 1) & 3)) << 4);
            ldmatrix_x4(af[mi][0], af[mi][1], af[mi][2], af[mi][3], addr);
        }
#pragma unroll
        for (int mi = 0; mi < 3; ++mi)
#pragma unroll
            for (int ni = 0; ni < 4; ++ni)
                mma_f16(acc[mi][ni], af[mi], bf[0][ni]);

        // ---- memory issue phase (overlaps MMA tail) ----
        const int s2 = kk + 2;
        if (s2 < KIT) sts_x(s2 & 3, s2, xvh);
        const int s3 = kk + 3;
        if (s3 < KIT) {
            ldg_x(s3, xvh);
            ldw(s3 & 3, s3);
        }
        asm volatile("cp.async.commit_group;" ::: "memory");

        // ---- X fragments ks1 + MMA burst 1 (skip on last half-window) ----
        if (kk != KIT - 1) {
#pragma unroll
            for (int mi = 0; mi < 3; ++mi) {
                int row = wm * 48 + mi * 16 + rl;
                uint32_t addr = xbase + row * XROW_B
                              + (((1 * 2 + hl) ^ ((row >> 1) & 3)) << 4);
                ldmatrix_x4(af[mi][0], af[mi][1], af[mi][2], af[mi][3], addr);
            }
#pragma unroll
            for (int mi = 0; mi < 3; ++mi)
#pragma unroll
                for (int ni = 0; ni < 4; ++ni)
                    mma_f16(acc[mi][ni], af[mi], bf[1][ni]);
        }
    }

    // ---- epilogue: bias add + guarded float2 stores ----
    const int gid = lane >> 2;
    const int tig = lane & 3;
    float* outb = out + (size_t)b * Tt * Nn;
    const float* bb = bias + s * Nn;
#pragma unroll
    for (int mi = 0; mi < 3; ++mi) {
        int r0 = m0 + wm * 48 + mi * 16 + gid;
#pragma unroll
        for (int ni = 0; ni < 4; ++ni) {
            int n = n0 + wn * 32 + ni * 8 + tig * 2;
            if (n < Nn) {
                float bv0 = bb[n];
                float bv1 = bb[n + 1];
                if (r0 < Tt) {
                    float2 v = make_float2(acc[mi][ni][0] + bv0, acc[mi][ni][1] + bv1);
                    *reinterpret_cast<float2*>(outb + (size_t)r0 * Nn + n) = v;
                }
                if (r0 + 8 < Tt) {
                    float2 v = make_float2(acc[mi][ni][2] + bv0, acc[mi][ni][3] + bv1);
                    *reinterpret_cast<float2*>(outb + (size_t)(r0 + 8) * Nn + n) = v;
                }
            }
        }
    }
}

extern "C" void kernel_launch(void* const* d_in, const int* in_sizes, int n_in,
                              void* d_out, int out_size) {
    const float* X    = (const float*)d_in[0];
    const void*  subj = d_in[1];
    const float* W    = (const float*)d_in[2];
    const float* bias = (const float*)d_in[3];
    float* out = (float*)d_out;

    cudaFuncSetAttribute(subj_gemm_kernel,
                         cudaFuncAttributeMaxDynamicSharedMemorySize, SMEM_BYTES);

    int prep_threads = 4 * NNB * NKC * 32;   // 73984
    prep_w_frag<<<(prep_threads + 255) / 256, 256>>>(W, (const unsigned int*)subj);

    dim3 grid((Nn + BN - 1) / BN,   // 3
              (Tt + BM - 1) / BM,   // 3
              Bb);                  // 2048
    subj_gemm_kernel<<<grid, dim3(THREADS), SMEM_BYTES>>>(X, subj, bias, out);
}

// round 17
// speedup vs baseline: 1.4702x; 1.0914x over previous
#include <cuda_runtime.h>
#include <cuda_fp16.h>
#include <cstdint>

// Problem constants
static constexpr int Bb = 2048, Tt = 281, Kk = 272, Nn = 272;

#define THREADS 192
static constexpr int BM = 96, BN = 96, BK = 32;      // CTA tile; BK floats of K per chunk
static constexpr int STAGES = 4;
static constexpr int KIT = 9;            // chunks per tile (last is 16-wide)
static constexpr int NKC = Kk / 16;      // 17 k16-chunks
static constexpr int NNB = Nn / 8;       // 34 n8-blocks
static constexpr int NBL = BN / 8;       // 12 n-blocks per CTA

// SMEM layout (bytes, dynamic):
// X stage: 96 rows x 64B (32 fp16), 16B units XOR-swizzled: unit' = unit ^ ((row>>1)&3)
static constexpr int XROW_B   = 64;
static constexpr int XSTAGE_B = BM * XROW_B;          // 6144
static constexpr int WSTAGE_B = NBL * 2 * 256;        // 6144
static constexpr int STAGE_B  = XSTAGE_B + WSTAGE_B;  // 12288
static constexpr int SMEM_BYTES = STAGES * STAGE_B;   // 49152

// Fragment-ordered fp16(RN) weights: per (e, nb, kc16, lane) one uint2
__device__ uint2 g_Wf[4 * NNB * NKC * 32];
__device__ int g_subj_is64;

// One-time W -> fragment-ordered fp16 layout (+ subject dtype probe in block 0)
__global__ void prep_w_frag(const float* __restrict__ W,
                            const unsigned int* __restrict__ subj_words) {
    if (blockIdx.x == 0 && threadIdx.x == 0) {
        int is64 = 1;
        for (int i = 1; i < 2048; i += 2)
            if (subj_words[i] != 0u) { is64 = 0; break; }
        g_subj_is64 = is64;
    }
    int idx = blockIdx.x * blockDim.x + threadIdx.x;
    if (idx >= 4 * NNB * NKC * 32) return;
    int lane = idx & 31;
    int kc   = (idx >> 5) % NKC;
    int nb   = ((idx >> 5) / NKC) % NNB;
    int e    = (idx >> 5) / (NKC * NNB);
    int gid = lane >> 2, tig = lane & 3;
    int n  = nb * 8 + gid;
    int k0 = kc * 16 + 2 * tig;
    const float* We = W + (size_t)e * Kk * Nn;
    __half2 h0 = __floats2half2_rn(We[(size_t)(k0    ) * Nn + n],
                                   We[(size_t)(k0 + 1) * Nn + n]);
    __half2 h1 = __floats2half2_rn(We[(size_t)(k0 + 8) * Nn + n],
                                   We[(size_t)(k0 + 9) * Nn + n]);
    uint2 u;
    u.x = *reinterpret_cast<uint32_t*>(&h0);
    u.y = *reinterpret_cast<uint32_t*>(&h1);
    g_Wf[((size_t)(e * NNB + nb) * NKC + kc) * 32 + lane] = u;
}

__device__ __forceinline__ void mma_f16(float* d, const uint32_t* a, const uint32_t* bfr) {
    asm volatile(
        "mma.sync.aligned.m16n8k16.row.col.f32.f16.f16.f32 "
        "{%0,%1,%2,%3}, {%4,%5,%6,%7}, {%8,%9}, {%0,%1,%2,%3};"
        : "+f"(d[0]), "+f"(d[1]), "+f"(d[2]), "+f"(d[3])
        : "r"(a[0]), "r"(a[1]), "r"(a[2]), "r"(a[3]), "r"(bfr[0]), "r"(bfr[1]));
}
__device__ __forceinline__ void cp_async16(uint32_t dst, const void* src, int sz) {
    asm volatile("cp.async.cg.shared.global [%0], [%1], 16, %2;\n"
                 :: "r"(dst), "l"(src), "r"(sz));
}
__device__ __forceinline__ void ldmatrix_x4(uint32_t& d0, uint32_t& d1,
                                            uint32_t& d2, uint32_t& d3, uint32_t addr) {
    asm volatile("ldmatrix.sync.aligned.m8n8.x4.shared.b16 {%0,%1,%2,%3}, [%4];"
                 : "=r"(d0), "=r"(d1), "=r"(d2), "=r"(d3) : "r"(addr));
}

__global__ __launch_bounds__(THREADS, 3) void subj_gemm_kernel(
    const float* __restrict__ X, const void* __restrict__ subj,
    const float* __restrict__ bias, float* __restrict__ out)
{
    extern __shared__ char smem[];
    const uint32_t xsmem = (uint32_t)__cvta_generic_to_shared(smem);

    const int b   = blockIdx.z;
    const int m0  = blockIdx.y * BM;
    const int nb0 = blockIdx.x * NBL;
    const int n0  = nb0 * 8;

    int s;
    if (g_subj_is64) s = (int)((const long long*)subj)[b];
    else             s = ((const int*)subj)[b];

    const float* Xb  = X + (size_t)b * Tt * Kk;
    const char*  Wfe = reinterpret_cast<const char*>(g_Wf + (size_t)s * NNB * NKC * 32);

    const int tid  = threadIdx.x;
    const int lane = tid & 31;
    const int warp = tid >> 5;     // 0..5
    const int wm   = warp / 3;     // 0..1
    const int wn   = warp % 3;     // 0..2
    const int rl   = lane & 15;    // ldmatrix row-in-frag
    const int hl   = lane >> 4;    // ldmatrix k-half select

    // X producer coords (coalesced): task c = tid + 192*it, it=0..3
    //   row = c>>3 = (tid>>3) + 24*it,  16B-unit-in-row = tid&7 (invariant over it)
    const int xu   = tid & 7;            // fp32 16B unit (0..7)
    const int u16  = xu >> 1;            // fp16 16B unit (0..3)
    const int h8   = xu & 1;             // 8B half within fp16 unit
    int xr[4], xm[4];
#pragma unroll
    for (int it = 0; it < 4; ++it) {
        xr[it] = (tid >> 3) + 24 * it;           // 0..95
        int m = m0 + xr[it];
        xm[it] = (m < Tt) ? m : (Tt - 1);
    }

    float acc[3][4][4];
#pragma unroll
    for (int i = 0; i < 3; ++i)
#pragma unroll
        for (int j = 0; j < 4; ++j)
#pragma unroll
            for (int k = 0; k < 4; ++k) acc[i][j][k] = 0.f;

    // ---- X: 4 coalesced LDG.128, held RAW (cvt deferred to STS time) ----
    auto ldg_x = [&](int ci, float4* xvf) {
        const int kf = ci * BK + xu * 4;
        if (kf < Kk) {
#pragma unroll
            for (int it = 0; it < 4; ++it)
                xvf[it] = *reinterpret_cast<const float4*>(Xb + (size_t)xm[it] * Kk + kf);
        }
    };
    // ---- X: cvt fp32->fp16 + 4x STS.64 into swizzled tile (a full chunk after LDG) ----
    auto sts_x = [&](int st, int ci, const float4* xvf) {
        const int kf = ci * BK + xu * 4;
        if (kf < Kk) {
            char* xbase = smem + st * STAGE_B;
#pragma unroll
            for (int it = 0; it < 4; ++it) {
                __half2 h0 = __floats2half2_rn(xvf[it].x, xvf[it].y);
                __half2 h1 = __floats2half2_rn(xvf[it].z, xvf[it].w);
                uint2 u;
                u.x = *reinterpret_cast<uint32_t*>(&h0);
                u.y = *reinterpret_cast<uint32_t*>(&h1);
                int r = xr[it];
                int off = r * XROW_B + ((u16 ^ ((r >> 1) & 3)) << 4) + h8 * 8;
                *reinterpret_cast<uint2*>(xbase + off) = u;
            }
        }
    };
    // ---- W: cp.async fragment chunks for k-window ci (2 x k16) ----
    auto ldw = [&](int st, int ci) {
        char* wbase = smem + st * STAGE_B + XSTAGE_B;
#pragma unroll
        for (int it = 0; it < 2; ++it) {
            int c   = tid + it * THREADS;         // 0..383
            int nbl = c >> 5;
            int ks  = (c >> 4) & 1;
            int ch  = c & 15;
            int nb  = nb0 + nbl;
            int kc  = ci * 2 + ks;
            bool v  = (nb < NNB) && (kc < NKC);
            const char* src = Wfe + ((size_t)(v ? nb : 0) * NKC + (v ? kc : 0)) * 256 + ch * 16;
            uint32_t dst = (uint32_t)__cvta_generic_to_shared(
                wbase + (nbl * 2 + ks) * 256 + ch * 16);
            cp_async16(dst, src, v ? 16 : 0);
        }
    };

    // ---- prologue ----
    float4 xvf[4];
    ldg_x(0, xvf); sts_x(0, 0, xvf);
    ldw(0, 0);
    asm volatile("cp.async.commit_group;" ::: "memory");
    ldg_x(1, xvf); sts_x(1, 1, xvf);
    ldw(1, 1);
    asm volatile("cp.async.commit_group;" ::: "memory");
    ldg_x(2, xvf);               // STS happens at iter 0
    ldw(2, 2);
    asm volatile("cp.async.commit_group;" ::: "memory");

    // ---- mainloop: fully unrolled; W fragments loaded per-ks ----
#pragma unroll
    for (int kk = 0; kk < KIT; ++kk) {
        asm volatile("cp.async.wait_group 2;" ::: "memory");
        __syncthreads();

        const int st = kk & 3;
        const uint32_t xbase = xsmem + st * STAGE_B;
        const char* wbase = smem + st * STAGE_B + XSTAGE_B;

        // ---- W + X fragments ks0 + MMA burst 0 ----
        uint32_t bf[4][2];
#pragma unroll
        for (int ni = 0; ni < 4; ++ni) {
            int nbl = wn * 4 + ni;
            uint2 v = *reinterpret_cast<const uint2*>(
                wbase + (nbl * 2) * 256 + lane * 8);
            bf[ni][0] = v.x;
            bf[ni][1] = v.y;
        }
        uint32_t af[3][4];
#pragma unroll
        for (int mi = 0; mi < 3; ++mi) {
            int row = wm * 48 + mi * 16 + rl;
            uint32_t addr = xbase + row * XROW_B
                          + (((0 * 2 + hl) ^ ((row >> 1) & 3)) << 4);
            ldmatrix_x4(af[mi][0], af[mi][1], af[mi][2], af[mi][3], addr);
        }
#pragma unroll
        for (int mi = 0; mi < 3; ++mi)
#pragma unroll
            for (int ni = 0; ni < 4; ++ni)
                mma_f16(acc[mi][ni], af[mi], bf[ni]);

        // ---- memory issue phase (overlaps MMA tail; cvts here consume
        //      LDGs issued a full chunk ago -> no exposed stall) ----
        const int s2 = kk + 2;
        if (s2 < KIT) sts_x(s2 & 3, s2, xvf);
        const int s3 = kk + 3;
        if (s3 < KIT) {
            ldg_x(s3, xvf);
            ldw(s3 & 3, s3);
        }
        asm volatile("cp.async.commit_group;" ::: "memory");

        // ---- W + X fragments ks1 + MMA burst 1 (skip on last half-window) ----
        if (kk != KIT - 1) {
#pragma unroll
            for (int ni = 0; ni < 4; ++ni) {
                int nbl = wn * 4 + ni;
                uint2 v = *reinterpret_cast<const uint2*>(
                    wbase + (nbl * 2 + 1) * 256 + lane * 8);
                bf[ni][0] = v.x;
                bf[ni][1] = v.y;
            }
#pragma unroll
            for (int mi = 0; mi < 3; ++mi) {
                int row = wm * 48 + mi * 16 + rl;
                uint32_t addr = xbase + row * XROW_B
                              + (((1 * 2 + hl) ^ ((row >> 1) & 3)) << 4);
                ldmatrix_x4(af[mi][0], af[mi][1], af[mi][2], af[mi][3], addr);
            }
#pragma unroll
            for (int mi = 0; mi < 3; ++mi)
#pragma unroll
                for (int ni = 0; ni < 4; ++ni)
                    mma_f16(acc[mi][ni], af[mi], bf[ni]);
        }
    }

    // ---- epilogue: bias add + guarded float2 stores ----
    const int gid = lane >> 2;
    const int tig = lane & 3;
    float* outb = out + (size_t)b * Tt * Nn;
    const float* bb = bias + s * Nn;
#pragma unroll
    for (int mi = 0; mi < 3; ++mi) {
        int r0 = m0 + wm * 48 + mi * 16 + gid;
#pragma unroll
        for (int ni = 0; ni < 4; ++ni) {
            int n = n0 + wn * 32 + ni * 8 + tig * 2;
            if (n < Nn) {
                float bv0 = bb[n];
                float bv1 = bb[n + 1];
                if (r0 < Tt) {
                    float2 v = make_float2(acc[mi][ni][0] + bv0, acc[mi][ni][1] + bv1);
                    *reinterpret_cast<float2*>(outb + (size_t)r0 * Nn + n) = v;
                }
                if (r0 + 8 < Tt) {
                    float2 v = make_float2(acc[mi][ni][2] + bv0, acc[mi][ni][3] + bv1);
                    *reinterpret_cast<float2*>(outb + (size_t)(r0 + 8) * Nn + n) = v;
                }
            }
        }
    }
}

extern "C" void kernel_launch(void* const* d_in, const int* in_sizes, int n_in,
                              void* d_out, int out_size) {
    const float* X    = (const float*)d_in[0];
    const void*  subj = d_in[1];
    const float* W    = (const float*)d_in[2];
    const float* bias = (const float*)d_in[3];
    float* out = (float*)d_out;

    cudaFuncSetAttribute(subj_gemm_kernel,
                         cudaFuncAttributeMaxDynamicSharedMemorySize, SMEM_BYTES);

    int prep_threads = 4 * NNB * NKC * 32;   // 73984
    prep_w_frag<<<(prep_threads + 255) / 256, 256>>>(W, (const unsigned int*)subj);

    dim3 grid((Nn + BN - 1) / BN,   // 3
              (Tt + BM - 1) / BM,   // 3
              Bb);                  // 2048
    subj_gemm_kernel<<<grid, dim3(THREADS), SMEM_BYTES>>>(X, subj, bias, out);
}